// round 1
// baseline (speedup 1.0000x reference)
#include <cuda_runtime.h>
#include <cstdint>

#define THRESH 1.25f

constexpr int B    = 16;
constexpr int CIN  = 8192;   // 64*64*2
constexpr int CHID = 512;
constexpr int COUT = 100;
constexpr int T    = 300;
constexpr int NW0  = CIN / 32;   // 256 words per (b,t) for input bits
constexpr int NW1  = CHID / 32;  // 16 words per (b,t) for hidden bits

// ---------------- scratch (static device globals; allocation-free) -------------
__device__ __align__(256) float    d_WT1[CIN * CHID];     // 16 MB  [i][o]
__device__ __align__(256) float    d_WT2[CHID * CHID];    // 1 MB   [i][o]
__device__ __align__(256) float    d_WT3[CHID * 128];     // 256 KB [i][o padded to 128]
__device__ __align__(256) float    d_scale1[CHID];
__device__ __align__(256) float    d_scale2[CHID];
__device__ __align__(256) float    d_scale3[COUT];
__device__ __align__(256) unsigned d_bits0[T * B * NW0];  // 4.9 MB input spikes bitpacked [t][b][w]
__device__ __align__(256) unsigned d_bits1[T * B * NW1];  // hidden spikes layer1
__device__ __align__(256) unsigned d_bits2[T * B * NW1];  // hidden spikes layer2
__device__ __align__(256) float    d_z [T * B * CHID];    // 9.8 MB  [t][b][o] (reused L1/L2)
__device__ __align__(256) float    d_z3[T * B * COUT];    // [t][b][c]

// ---------------- row norms: scale[o] = g[o] / ||v[o,:]|| ----------------------
template <int L>
__global__ void row_norm(const float* __restrict__ v, const float* __restrict__ g)
{
    constexpr int NI = (L == 0) ? CIN : CHID;
    float* scale = (L == 0) ? d_scale1 : (L == 1) ? d_scale2 : d_scale3;
    int r = blockIdx.x;
    const float* row = v + (size_t)r * NI;
    float s = 0.f;
    for (int i = threadIdx.x; i < NI; i += 256) { float x = row[i]; s = fmaf(x, x, s); }
    #pragma unroll
    for (int d = 16; d > 0; d >>= 1) s += __shfl_down_sync(0xffffffffu, s, d);
    __shared__ float red[8];
    int lane = threadIdx.x & 31, w = threadIdx.x >> 5;
    if (lane == 0) red[w] = s;
    __syncthreads();
    if (threadIdx.x == 0) {
        float tot = 0.f;
        #pragma unroll
        for (int j = 0; j < 8; j++) tot += red[j];
        scale[r] = g[r] / sqrtf(tot);
    }
}

// ---------------- transpose + scale: WT[i][o] = v[o][i] * scale[o] -------------
template <int L>
__global__ void wnorm_transpose(const float* __restrict__ v)
{
    constexpr int NI      = (L == 0) ? CIN : CHID;
    constexpr int OSTRIDE = (L == 2) ? 128 : CHID;
    constexpr int NOV     = (L == 2) ? COUT : CHID;
    float* wt = (L == 0) ? d_WT1 : (L == 1) ? d_WT2 : d_WT3;
    const float* scale = (L == 0) ? d_scale1 : (L == 1) ? d_scale2 : d_scale3;

    __shared__ float tile[32][33];
    int i0 = blockIdx.x * 32, o0 = blockIdx.y * 32;
    int tx = threadIdx.x, ty = threadIdx.y;
    #pragma unroll
    for (int k = 0; k < 4; k++) {
        int o = o0 + ty + k * 8;
        tile[ty + k * 8][tx] = (o < NOV) ? v[(size_t)o * NI + i0 + tx] : 0.f;
    }
    __syncthreads();
    #pragma unroll
    for (int k = 0; k < 4; k++) {
        int i = i0 + ty + k * 8;
        int o = o0 + tx;
        float s = (o < NOV) ? scale[o] : 0.f;
        wt[(size_t)i * OSTRIDE + o] = tile[tx][ty + k * 8] * s;
    }
}

// ---------------- bitpack input spikes [b][i][t] -> bits [t][b][i/32] ----------
// warp handles (b, 32-i group, 32-t chunk); lane = i offset; float4 reads over t
__global__ void bitpack_in(const float* __restrict__ spike)
{
    int warpId = (blockIdx.x * blockDim.x + threadIdx.x) >> 5;
    int lane   = threadIdx.x & 31;
    int tc = warpId % 10;
    int ig = (warpId / 10) % (CIN / 32);
    int b  = warpId / (10 * (CIN / 32));
    int i  = ig * 32 + lane;
    int t0 = tc * 32;

    const float4* sp4 = (const float4*)(spike + ((size_t)b * CIN + i) * T);
    float4 v[8];
    #pragma unroll
    for (int j = 0; j < 8; j++) {
        int tt = t0 + 4 * j;
        v[j] = (tt < T) ? sp4[tt >> 2] : make_float4(0.f, 0.f, 0.f, 0.f);
    }
    #pragma unroll
    for (int j = 0; j < 8; j++) {
        float4 q = v[j];
        unsigned m0 = __ballot_sync(0xffffffffu, q.x > 0.5f);
        unsigned m1 = __ballot_sync(0xffffffffu, q.y > 0.5f);
        unsigned m2 = __ballot_sync(0xffffffffu, q.z > 0.5f);
        unsigned m3 = __ballot_sync(0xffffffffu, q.w > 0.5f);
        int tb = t0 + 4 * j;
        if (lane == 4 * j + 0 && tb + 0 < T) d_bits0[(size_t)(tb + 0) * (B * NW0) + b * NW0 + ig] = m0;
        if (lane == 4 * j + 1 && tb + 1 < T) d_bits0[(size_t)(tb + 1) * (B * NW0) + b * NW0 + ig] = m1;
        if (lane == 4 * j + 2 && tb + 2 < T) d_bits0[(size_t)(tb + 2) * (B * NW0) + b * NW0 + ig] = m2;
        if (lane == 4 * j + 3 && tb + 3 < T) d_bits0[(size_t)(tb + 3) * (B * NW0) + b * NW0 + ig] = m3;
    }
}

// ---------------- sparse gather GEMM: z[t][b][:] = sum_{i active} WT[i][:] -----
// one block per (t,b); 128 threads x float4 = 512 outputs; deterministic order
template <int L>
__global__ void gather_hid()
{
    constexpr int NWORDS = (L == 0) ? NW0 : NW1;
    const unsigned* __restrict__ bitsall = (L == 0) ? d_bits0 : d_bits1;
    const float4*   __restrict__ wt = (const float4*)((L == 0) ? d_WT1 : d_WT2);

    int t = blockIdx.x, b = blockIdx.y;
    const unsigned* bp = bitsall + ((size_t)t * B + b) * NWORDS;

    __shared__ unsigned short sidx[NWORDS * 32];
    __shared__ int scount;
    int tid = threadIdx.x, lane = tid & 31;

    if (tid < 32) {  // warp 0 builds the index list deterministically
        int running = 0;
        #pragma unroll
        for (int wb = 0; wb < NWORDS; wb += 32) {
            int w = wb + lane;
            unsigned m = (w < NWORDS) ? bp[w] : 0u;
            int c = __popc(m);
            int x = c;
            #pragma unroll
            for (int d = 1; d < 32; d <<= 1) {
                int y = __shfl_up_sync(0xffffffffu, x, d);
                if (lane >= d) x += y;
            }
            int base = running + x - c;
            running += __shfl_sync(0xffffffffu, x, 31);
            while (m) {
                int bpos = __ffs((int)m) - 1;
                m &= m - 1;
                sidx[base++] = (unsigned short)(w * 32 + bpos);
            }
        }
        if (lane == 0) scount = running;
    }
    __syncthreads();

    int cnt = scount;
    float ax = 0.f, ay = 0.f, az = 0.f, aw = 0.f;
    int k = 0;
    for (; k + 8 <= cnt; k += 8) {
        float4 r[8];
        #pragma unroll
        for (int u = 0; u < 8; u++) { int i = sidx[k + u]; r[u] = wt[i * 128 + tid]; }
        #pragma unroll
        for (int u = 0; u < 8; u++) { ax += r[u].x; ay += r[u].y; az += r[u].z; aw += r[u].w; }
    }
    for (; k < cnt; k++) {
        int i = sidx[k];
        float4 r0 = wt[i * 128 + tid];
        ax += r0.x; ay += r0.y; az += r0.z; aw += r0.w;
    }
    float4 o; o.x = ax; o.y = ay; o.z = az; o.w = aw;
    ((float4*)d_z)[((size_t)t * B + b) * 128 + tid] = o;
}

// layer 3: 100 outputs (padded to 128), scalar accumulators
__global__ void gather_out()
{
    int t = blockIdx.x, b = blockIdx.y;
    const unsigned* bp = d_bits2 + ((size_t)t * B + b) * NW1;

    __shared__ unsigned short sidx[NW1 * 32];
    __shared__ int scount;
    int tid = threadIdx.x, lane = tid & 31;

    if (tid < 32) {
        unsigned m = (lane < NW1) ? bp[lane] : 0u;
        int c = __popc(m);
        int x = c;
        #pragma unroll
        for (int d = 1; d < 32; d <<= 1) {
            int y = __shfl_up_sync(0xffffffffu, x, d);
            if (lane >= d) x += y;
        }
        int base = x - c;
        while (m) {
            int bpos = __ffs((int)m) - 1;
            m &= m - 1;
            sidx[base++] = (unsigned short)(lane * 32 + bpos);
        }
        if (lane == 31) scount = x;
    }
    __syncthreads();

    int cnt = scount;
    float acc = 0.f;
    int k = 0;
    for (; k + 8 <= cnt; k += 8) {
        float r[8];
        #pragma unroll
        for (int u = 0; u < 8; u++) { int i = sidx[k + u]; r[u] = d_WT3[i * 128 + tid]; }
        #pragma unroll
        for (int u = 0; u < 8; u++) acc += r[u];
    }
    for (; k < cnt; k++) acc += d_WT3[sidx[k] * 128 + tid];

    if (tid < COUT) d_z3[((size_t)t * B + b) * COUT + tid] = acc;
}

// ---------------- LIF recurrence over T, hidden layers -> bitmasks -------------
template <int L>
__global__ void lif_hid(const float* __restrict__ cds, const float* __restrict__ vds)
{
    unsigned* bitsout = (L == 0) ? d_bits1 : d_bits2;
    int gid  = blockIdx.x * blockDim.x + threadIdx.x;  // 0..8191 = b*512+o
    int lane = threadIdx.x & 31;
    float a  = 1.f - cds[L];
    float bb = 1.f - vds[L];
    float cur = 0.f, volt = 0.f;
    float z0 = d_z[gid];
    float z1 = d_z[(size_t)(B * CHID) + gid];
    for (int t = 0; t < T; t++) {
        float zt = z0;
        z0 = z1;
        z1 = (t + 2 < T) ? d_z[(size_t)(t + 2) * (B * CHID) + gid] : 0.f;
        cur  = fmaf(a, cur, zt);
        volt = fmaf(bb, volt, cur);
        bool s = volt >= THRESH;
        unsigned m = __ballot_sync(0xffffffffu, s);
        volt = s ? 0.f : volt;
        if (lane == 0) bitsout[(size_t)t * (B * NW1) + (gid >> 5)] = m;
    }
}

// ---------------- LIF output layer -> d_out [b][c][t] float --------------------
__global__ void lif_out(const float* __restrict__ cds, const float* __restrict__ vds,
                        float* __restrict__ out)
{
    int gid = blockIdx.x * blockDim.x + threadIdx.x;
    if (gid >= B * COUT) return;
    int b = gid / COUT, c = gid % COUT;
    float a  = 1.f - cds[2];
    float bb = 1.f - vds[2];
    float cur = 0.f, volt = 0.f;
    float* orow = out + ((size_t)b * COUT + c) * T;
    float z0 = d_z3[gid];
    float z1 = d_z3[(size_t)(B * COUT) + gid];
    for (int t = 0; t < T; t++) {
        float zt = z0;
        z0 = z1;
        z1 = (t + 2 < T) ? d_z3[(size_t)(t + 2) * (B * COUT) + gid] : 0.f;
        cur  = fmaf(a, cur, zt);
        volt = fmaf(bb, volt, cur);
        bool s = volt >= THRESH;
        volt = s ? 0.f : volt;
        orow[t] = s ? 1.0f : 0.0f;
    }
}

// ---------------- launch ---------------------------------------------------------
extern "C" void kernel_launch(void* const* d_in, const int* in_sizes, int n_in,
                              void* d_out, int out_size)
{
    const float* spike = (const float*)d_in[0];
    const float* v1 = (const float*)d_in[1];
    const float* g1 = (const float*)d_in[2];
    const float* v2 = (const float*)d_in[3];
    const float* g2 = (const float*)d_in[4];
    const float* v3 = (const float*)d_in[5];
    const float* g3 = (const float*)d_in[6];
    const float* cds = (const float*)d_in[7];
    const float* vds = (const float*)d_in[8];
    float* out = (float*)d_out;

    // weight prep
    row_norm<0><<<CHID, 256>>>(v1, g1);
    row_norm<1><<<CHID, 256>>>(v2, g2);
    row_norm<2><<<COUT, 256>>>(v3, g3);
    wnorm_transpose<0><<<dim3(CIN / 32, CHID / 32), dim3(32, 8)>>>(v1);
    wnorm_transpose<1><<<dim3(CHID / 32, CHID / 32), dim3(32, 8)>>>(v2);
    wnorm_transpose<2><<<dim3(CHID / 32, 128 / 32), dim3(32, 8)>>>(v3);

    // spike bitpack: 16 * 256 * 10 warps, 4 warps/block
    bitpack_in<<<(B * (CIN / 32) * 10) / 4, 128>>>(spike);

    // layer 1
    gather_hid<0><<<dim3(T, B), 128>>>();
    lif_hid<0><<<(B * CHID) / 256, 256>>>(cds, vds);
    // layer 2
    gather_hid<1><<<dim3(T, B), 128>>>();
    lif_hid<1><<<(B * CHID) / 256, 256>>>(cds, vds);
    // layer 3
    gather_out<<<dim3(T, B), 128>>>();
    lif_out<<<(B * COUT + 127) / 128, 128>>>(cds, vds, out);
}

// round 2
// speedup vs baseline: 1.1385x; 1.1385x over previous
#include <cuda_runtime.h>
#include <cstdint>

#define THRESH 1.25f

constexpr int B    = 16;
constexpr int CIN  = 8192;   // 64*64*2
constexpr int CHID = 512;
constexpr int COUT = 100;
constexpr int T    = 300;
constexpr int NW0  = CIN / 32;   // 256 words per (b,t) for input bits
constexpr int NW1  = CHID / 32;  // 16 words per (b,t) for hidden bits

// ---------------- scratch (static device globals; allocation-free) -------------
__device__ __align__(256) float    d_WT1[CIN * CHID];     // 16 MB  [i][o]
__device__ __align__(256) float    d_WT2[CHID * CHID];    // 1 MB   [i][o]
__device__ __align__(256) float    d_WT3[CHID * 128];     // 256 KB [i][o padded to 128]
__device__ __align__(256) float    d_scale1[CHID];
__device__ __align__(256) float    d_scale2[CHID];
__device__ __align__(256) float    d_scale3[128];
__device__ __align__(256) unsigned d_bits0[T * B * NW0];  // 4.9 MB input spikes bitpacked [t][b][w]
__device__ __align__(256) unsigned d_bits1[T * B * NW1];  // hidden spikes layer1
__device__ __align__(256) unsigned d_bits2[T * B * NW1];  // hidden spikes layer2
__device__ __align__(256) float    d_z [T * B * CHID];    // 9.8 MB  [t][b][o]
__device__ __align__(256) float    d_z3[T * B * COUT];    // [t][b][c]

// ---------------- row norms: scale[o] = g[o] / ||v[o,:]|| ----------------------
template <int L>
__global__ void row_norm(const float* __restrict__ v, const float* __restrict__ g)
{
    constexpr int NI = (L == 0) ? CIN : CHID;
    float* scale = (L == 0) ? d_scale1 : (L == 1) ? d_scale2 : d_scale3;
    int r = blockIdx.x;
    const float* row = v + (size_t)r * NI;
    float s = 0.f;
    for (int i = threadIdx.x; i < NI; i += 256) { float x = row[i]; s = fmaf(x, x, s); }
    #pragma unroll
    for (int d = 16; d > 0; d >>= 1) s += __shfl_down_sync(0xffffffffu, s, d);
    __shared__ float red[8];
    int lane = threadIdx.x & 31, w = threadIdx.x >> 5;
    if (lane == 0) red[w] = s;
    __syncthreads();
    if (threadIdx.x == 0) {
        float tot = 0.f;
        #pragma unroll
        for (int j = 0; j < 8; j++) tot += red[j];
        scale[r] = g[r] / sqrtf(tot);
    }
}

// ---------------- transpose + scale: WT[i][o] = v[o][i] * scale[o] -------------
// 64x64 tiles, float4 reads along i, float4 writes along o
template <int L>
__global__ void wnorm_transpose(const float* __restrict__ v)
{
    constexpr int NI      = (L == 0) ? CIN : CHID;
    constexpr int OSTRIDE = (L == 2) ? 128 : CHID;
    constexpr int NOV     = (L == 2) ? COUT : CHID;
    float* wt = (L == 0) ? d_WT1 : (L == 1) ? d_WT2 : d_WT3;
    const float* scale = (L == 0) ? d_scale1 : (L == 1) ? d_scale2 : d_scale3;

    __shared__ float tile[64][65];   // [i_local][o_local]
    int i0 = blockIdx.x * 64, o0 = blockIdx.y * 64;
    int tid = threadIdx.x;
    int oy = tid >> 4;          // 0..15
    int ix = (tid & 15) * 4;    // 0..60

    #pragma unroll
    for (int k = 0; k < 4; k++) {
        int ol = oy + k * 16;
        int o  = o0 + ol;
        float4 val = make_float4(0.f, 0.f, 0.f, 0.f);
        if (o < NOV) val = *(const float4*)&v[(size_t)o * NI + i0 + ix];
        tile[ix + 0][ol] = val.x;
        tile[ix + 1][ol] = val.y;
        tile[ix + 2][ol] = val.z;
        tile[ix + 3][ol] = val.w;
    }
    __syncthreads();

    int iy = tid >> 4;          // 0..15
    int ox = (tid & 15) * 4;    // 0..60
    float4 sc;
    sc.x = (o0 + ox + 0 < NOV) ? scale[o0 + ox + 0] : 0.f;
    sc.y = (o0 + ox + 1 < NOV) ? scale[o0 + ox + 1] : 0.f;
    sc.z = (o0 + ox + 2 < NOV) ? scale[o0 + ox + 2] : 0.f;
    sc.w = (o0 + ox + 3 < NOV) ? scale[o0 + ox + 3] : 0.f;
    #pragma unroll
    for (int k = 0; k < 4; k++) {
        int il = iy + k * 16;
        float4 w;
        w.x = tile[il][ox + 0] * sc.x;
        w.y = tile[il][ox + 1] * sc.y;
        w.z = tile[il][ox + 2] * sc.z;
        w.w = tile[il][ox + 3] * sc.w;
        *(float4*)&wt[(size_t)(i0 + il) * OSTRIDE + o0 + ox] = w;
    }
}

// ---------------- bitpack input spikes [b][i][t] -> bits [t][b][i/32] ----------
__global__ void bitpack_in(const float* __restrict__ spike)
{
    int warpId = (blockIdx.x * blockDim.x + threadIdx.x) >> 5;
    int lane   = threadIdx.x & 31;
    int tc = warpId % 10;
    int ig = (warpId / 10) % (CIN / 32);
    int b  = warpId / (10 * (CIN / 32));
    int i  = ig * 32 + lane;
    int t0 = tc * 32;

    const float4* sp4 = (const float4*)(spike + ((size_t)b * CIN + i) * T);
    float4 v[8];
    #pragma unroll
    for (int j = 0; j < 8; j++) {
        int tt = t0 + 4 * j;
        v[j] = (tt < T) ? sp4[tt >> 2] : make_float4(0.f, 0.f, 0.f, 0.f);
    }
    #pragma unroll
    for (int j = 0; j < 8; j++) {
        float4 q = v[j];
        unsigned m0 = __ballot_sync(0xffffffffu, q.x > 0.5f);
        unsigned m1 = __ballot_sync(0xffffffffu, q.y > 0.5f);
        unsigned m2 = __ballot_sync(0xffffffffu, q.z > 0.5f);
        unsigned m3 = __ballot_sync(0xffffffffu, q.w > 0.5f);
        int tb = t0 + 4 * j;
        if (lane == 4 * j + 0 && tb + 0 < T) d_bits0[(size_t)(tb + 0) * (B * NW0) + b * NW0 + ig] = m0;
        if (lane == 4 * j + 1 && tb + 1 < T) d_bits0[(size_t)(tb + 1) * (B * NW0) + b * NW0 + ig] = m1;
        if (lane == 4 * j + 2 && tb + 2 < T) d_bits0[(size_t)(tb + 2) * (B * NW0) + b * NW0 + ig] = m2;
        if (lane == 4 * j + 3 && tb + 3 < T) d_bits0[(size_t)(tb + 3) * (B * NW0) + b * NW0 + ig] = m3;
    }
}

// ---------------- sparse gather GEMM: z[t][b][:] = sum_{i active} WT[i][:] -----
// one block per (t,b); 256 threads x float2 = 512 outputs
// 8-warp parallel index-list build (deterministic ascending-i order)
template <int L>
__global__ void gather_hid()
{
    constexpr int NWORDS = (L == 0) ? NW0 : NW1;
    const unsigned* __restrict__ bitsall = (L == 0) ? d_bits0 : d_bits1;
    const float2*   __restrict__ wt = (const float2*)((L == 0) ? d_WT1 : d_WT2);

    int t = blockIdx.x, b = blockIdx.y;
    const unsigned* bp = bitsall + ((size_t)t * B + b) * NWORDS;

    __shared__ unsigned short sidx[NWORDS * 32];
    __shared__ int wcnt[8];
    int tid = threadIdx.x, lane = tid & 31, w = tid >> 5;

    int word = w * 32 + lane;
    unsigned m = (word < NWORDS) ? bp[word] : 0u;
    int c = __popc(m);
    int x = c;  // inclusive prefix within warp
    #pragma unroll
    for (int d = 1; d < 32; d <<= 1) {
        int y = __shfl_up_sync(0xffffffffu, x, d);
        if (lane >= d) x += y;
    }
    if (lane == 31) wcnt[w] = x;
    __syncthreads();

    int base = 0, cnt = 0;
    #pragma unroll
    for (int j = 0; j < 8; j++) {
        int wc = wcnt[j];
        if (j < w) base += wc;
        cnt += wc;
    }
    int mybase = base + x - c;
    while (m) {
        int bpos = __ffs((int)m) - 1;
        m &= m - 1;
        sidx[mybase++] = (unsigned short)(word * 32 + bpos);
    }
    __syncthreads();

    float ax = 0.f, ay = 0.f;
    int k = 0;
    for (; k + 8 <= cnt; k += 8) {
        float2 r[8];
        #pragma unroll
        for (int u = 0; u < 8; u++) { int i = sidx[k + u]; r[u] = wt[i * 256 + tid]; }
        #pragma unroll
        for (int u = 0; u < 8; u++) { ax += r[u].x; ay += r[u].y; }
    }
    for (; k < cnt; k++) {
        float2 r0 = wt[sidx[k] * 256 + tid];
        ax += r0.x; ay += r0.y;
    }
    float2 o; o.x = ax; o.y = ay;
    ((float2*)d_z)[((size_t)t * B + b) * 256 + tid] = o;
}

// layer 3: 100 outputs (padded to 128), scalar accumulators, 128 threads
__global__ void gather_out()
{
    int t = blockIdx.x, b = blockIdx.y;
    const unsigned* bp = d_bits2 + ((size_t)t * B + b) * NW1;

    __shared__ unsigned short sidx[NW1 * 32];
    __shared__ int scount;
    int tid = threadIdx.x, lane = tid & 31;

    if (tid < 32) {
        unsigned m = (lane < NW1) ? bp[lane] : 0u;
        int c = __popc(m);
        int x = c;
        #pragma unroll
        for (int d = 1; d < 32; d <<= 1) {
            int y = __shfl_up_sync(0xffffffffu, x, d);
            if (lane >= d) x += y;
        }
        int base = x - c;
        while (m) {
            int bpos = __ffs((int)m) - 1;
            m &= m - 1;
            sidx[base++] = (unsigned short)(lane * 32 + bpos);
        }
        if (lane == 31) scount = x;
    }
    __syncthreads();

    int cnt = scount;
    float acc = 0.f;
    int k = 0;
    for (; k + 8 <= cnt; k += 8) {
        float r[8];
        #pragma unroll
        for (int u = 0; u < 8; u++) { int i = sidx[k + u]; r[u] = d_WT3[i * 128 + tid]; }
        #pragma unroll
        for (int u = 0; u < 8; u++) acc += r[u];
    }
    for (; k < cnt; k++) acc += d_WT3[sidx[k] * 128 + tid];

    if (tid < COUT) d_z3[((size_t)t * B + b) * COUT + tid] = acc;
}

// ---------------- LIF recurrence over T, hidden layers -> bitmasks -------------
// depth-4 prefetch ring; 128-thread blocks for wider SM spread
template <int L>
__global__ void lif_hid(const float* __restrict__ cds, const float* __restrict__ vds)
{
    unsigned* bitsout = (L == 0) ? d_bits1 : d_bits2;
    int gid  = blockIdx.x * blockDim.x + threadIdx.x;  // 0..8191 = b*512+o
    int lane = threadIdx.x & 31;
    float a  = 1.f - cds[L];
    float bb = 1.f - vds[L];
    float cur = 0.f, volt = 0.f;

    float zbuf[4];
    #pragma unroll
    for (int j = 0; j < 4; j++) zbuf[j] = d_z[(size_t)j * (B * CHID) + gid];

    #pragma unroll 4
    for (int t = 0; t < T; t++) {
        float zt = zbuf[t & 3];
        int tp = t + 4;
        zbuf[t & 3] = (tp < T) ? d_z[(size_t)tp * (B * CHID) + gid] : 0.f;
        cur  = fmaf(a, cur, zt);
        volt = fmaf(bb, volt, cur);
        bool s = volt >= THRESH;
        unsigned msk = __ballot_sync(0xffffffffu, s);
        volt = s ? 0.f : volt;
        if (lane == 0) bitsout[(size_t)t * (B * NW1) + (gid >> 5)] = msk;
    }
}

// ---------------- LIF output layer -> d_out [b][c][t] float --------------------
__global__ void lif_out(const float* __restrict__ cds, const float* __restrict__ vds,
                        float* __restrict__ out)
{
    int gid = blockIdx.x * blockDim.x + threadIdx.x;
    if (gid >= B * COUT) return;
    int b = gid / COUT, c = gid % COUT;
    float a  = 1.f - cds[2];
    float bb = 1.f - vds[2];
    float cur = 0.f, volt = 0.f;
    float* orow = out + ((size_t)b * COUT + c) * T;

    float zbuf[4];
    #pragma unroll
    for (int j = 0; j < 4; j++) zbuf[j] = d_z3[(size_t)j * (B * COUT) + gid];

    #pragma unroll 4
    for (int t = 0; t < T; t++) {
        float zt = zbuf[t & 3];
        int tp = t + 4;
        zbuf[t & 3] = (tp < T) ? d_z3[(size_t)tp * (B * COUT) + gid] : 0.f;
        cur  = fmaf(a, cur, zt);
        volt = fmaf(bb, volt, cur);
        bool s = volt >= THRESH;
        volt = s ? 0.f : volt;
        orow[t] = s ? 1.0f : 0.0f;
    }
}

// ---------------- launch ---------------------------------------------------------
extern "C" void kernel_launch(void* const* d_in, const int* in_sizes, int n_in,
                              void* d_out, int out_size)
{
    const float* spike = (const float*)d_in[0];
    const float* v1 = (const float*)d_in[1];
    const float* g1 = (const float*)d_in[2];
    const float* v2 = (const float*)d_in[3];
    const float* g2 = (const float*)d_in[4];
    const float* v3 = (const float*)d_in[5];
    const float* g3 = (const float*)d_in[6];
    const float* cds = (const float*)d_in[7];
    const float* vds = (const float*)d_in[8];
    float* out = (float*)d_out;

    // weight prep
    row_norm<0><<<CHID, 256>>>(v1, g1);
    row_norm<1><<<CHID, 256>>>(v2, g2);
    row_norm<2><<<COUT, 256>>>(v3, g3);
    wnorm_transpose<0><<<dim3(CIN / 64, CHID / 64), 256>>>(v1);
    wnorm_transpose<1><<<dim3(CHID / 64, CHID / 64), 256>>>(v2);
    wnorm_transpose<2><<<dim3(CHID / 64, 2), 256>>>(v3);

    // spike bitpack
    bitpack_in<<<(B * (CIN / 32) * 10) / 4, 128>>>(spike);

    // layer 1
    gather_hid<0><<<dim3(T, B), 256>>>();
    lif_hid<0><<<(B * CHID) / 128, 128>>>(cds, vds);
    // layer 2
    gather_hid<1><<<dim3(T, B), 256>>>();
    lif_hid<1><<<(B * CHID) / 128, 128>>>(cds, vds);
    // layer 3
    gather_out<<<dim3(T, B), 128>>>();
    lif_out<<<(B * COUT + 127) / 128, 128>>>(cds, vds, out);
}